// round 5
// baseline (speedup 1.0000x reference)
#include <cuda_runtime.h>
#include <math.h>

#define NUM_EXPERTS 16
#define FREQ_BINS   2097152
#define ROW_V       (FREQ_BINS / 4)          // 524288 float4 per row = 2^19
#define TPB         256
#define ITERS       8
#define BLOCKS_X    (ROW_V / (TPB * ITERS))  // 256
#define NBLOCKS     (BLOCKS_X * NUM_EXPERTS) // 4096

__device__ int      g_bounds[2 * NUM_EXPERTS];
__device__ int      g_flag = 0;              // release/acquire handshake
__device__ unsigned g_done = 0;              // replay-reset counter

// Single kernel. Block (0,0) warp 0 computes bounds (byte-identical math to
// all passing rounds: double tanh logistic -> f32 -> *2097151.0f -> trunc),
// release-publishes via g_flag. All blocks acquire-spin on the flag (thread 0
// only), then run the proven STG.128 write stream. Last block to finish
// resets flag+counter so every graph replay starts from clean state.
__global__ void __launch_bounds__(TPB) freq_bands_one(
    const float* __restrict__ bp, float4* __restrict__ out)
{
    const int tid = threadIdx.x;

    // ---- Leader prep: block (0,0), warp 0 ----
    if (blockIdx.x == 0 && blockIdx.y == 0 && tid < 32) {
        float my = 0.0f;
        if (tid < NUM_EXPERTS - 1) {
            double x = (double)bp[tid];
            my = (float)(0.5 + 0.5 * tanh(0.5 * x));
        }
        float b[NUM_EXPERTS + 1];
        b[0] = 0.0f;
        b[NUM_EXPERTS] = 1.0f;
#pragma unroll
        for (int i = 0; i < NUM_EXPERTS - 1; i++)
            b[i + 1] = __shfl_sync(0xFFFFFFFFu, my, i);

        if (tid == 0) {
            for (int i = 1; i <= NUM_EXPERTS; i++) {   // insertion sort, 17
                float key = b[i];
                int j = i - 1;
                while (j >= 0 && b[j] > key) { b[j + 1] = b[j]; j--; }
                b[j + 1] = key;
            }
#pragma unroll
            for (int e = 0; e < NUM_EXPERTS; e++) {
                g_bounds[2 * e]     = (int)(b[e] * 2097151.0f);
                g_bounds[2 * e + 1] = (e < NUM_EXPERTS - 1)
                                        ? (int)(b[e + 1] * 2097151.0f)
                                        : FREQ_BINS;
            }
            __threadfence();                 // release
            atomicExch(&g_flag, 1);          // publish
        }
    }

    // ---- All blocks: acquire-spin until bounds are published ----
    if (tid == 0) {
        int f;
        do {
            asm volatile("ld.acquire.gpu.b32 %0, [%1];"
                         : "=r"(f) : "l"(&g_flag) : "memory");
        } while (f == 0);
    }
    __syncthreads();                         // broadcast the acquire to the CTA

    // ---- Write stream (unchanged: measured at the HBM write ceiling) ----
    const int e  = blockIdx.y;
    const int s  = g_bounds[2 * e];
    const unsigned len = (unsigned)(g_bounds[2 * e + 1] - s);

    float4* row = out + (size_t)e * ROW_V;
    const unsigned base = blockIdx.x * (TPB * ITERS) + tid;

#pragma unroll
    for (int i = 0; i < ITERS; i++) {
        unsigned v = base + i * TPB;
        int p = (int)(v << 2) - s;
        float4 f;
        f.x = ((unsigned)(p    ) < len) ? 1.0f : 0.0f;
        f.y = ((unsigned)(p + 1) < len) ? 1.0f : 0.0f;
        f.z = ((unsigned)(p + 2) < len) ? 1.0f : 0.0f;
        f.w = ((unsigned)(p + 3) < len) ? 1.0f : 0.0f;
        row[v] = f;
    }

    // ---- Replay reset: last block to arrive clears the handshake state ----
    if (tid == 0) {
        unsigned t = atomicAdd(&g_done, 1);
        if (t == NBLOCKS - 1) {
            g_done = 0;
            atomicExch(&g_flag, 0);
        }
    }
}

extern "C" void kernel_launch(void* const* d_in, const int* in_sizes, int n_in,
                              void* d_out, int out_size) {
    const float* bound_params = (const float*)d_in[0];
    float4* out = (float4*)d_out;

    dim3 grid(BLOCKS_X, NUM_EXPERTS);        // (256, 16) x 256 threads
    freq_bands_one<<<grid, TPB>>>(bound_params, out);
}

// round 6
// speedup vs baseline: 1.0200x; 1.0200x over previous
#include <cuda_runtime.h>
#include <math.h>

#define NUM_EXPERTS 16
#define FREQ_BINS   2097152
#define ROW_V       (FREQ_BINS / 4)          // 524288 float4 per row = 2^19
#define TPB         256
#define ITERS       32                       // float4 stores per thread
#define BLOCKS_X    (ROW_V / (TPB * ITERS))  // 64 -> grid (64,16) = 1024 blocks
                                             // 1024 <= 148 SMs * 8 resident: ONE wave

__device__ int g_bounds[2 * NUM_EXPERTS];    // [start_e, end_e] pairs

// Prep: ONE warp, no smem. Lanes 0..14 compute double-precision sigmoids in
// parallel (XLA logistic = 0.5 + 0.5*tanh(0.5x), cast f32 — byte-identical to
// every passing round, rel_err=0.0). Lane 0 gathers via shfl, sorts, writes
// bounds, fences, then TRIGGERS the PDL dependency so masks unparks before
// this kernel's teardown.
__global__ void prep_kernel(const float* __restrict__ bp) {
    const int lane = threadIdx.x;

    float my = 0.0f;
    if (lane < NUM_EXPERTS - 1) {
        double x = (double)bp[lane];
        my = (float)(0.5 + 0.5 * tanh(0.5 * x));
    }

    float b[NUM_EXPERTS + 1];
    b[0] = 0.0f;
    b[NUM_EXPERTS] = 1.0f;
#pragma unroll
    for (int i = 0; i < NUM_EXPERTS - 1; i++)
        b[i + 1] = __shfl_sync(0xFFFFFFFFu, my, i);

    if (lane == 0) {
        for (int i = 1; i <= NUM_EXPERTS; i++) {   // insertion sort, 17 elems
            float key = b[i];
            int j = i - 1;
            while (j >= 0 && b[j] > key) { b[j + 1] = b[j]; j--; }
            b[j + 1] = key;
        }
#pragma unroll
        for (int e = 0; e < NUM_EXPERTS; e++) {
            g_bounds[2 * e]     = (int)(b[e] * 2097151.0f);   // f32 mul + trunc
            g_bounds[2 * e + 1] = (e < NUM_EXPERTS - 1)
                                    ? (int)(b[e + 1] * 2097151.0f)
                                    : FREQ_BINS;
        }
        __threadfence();
#if __CUDA_ARCH__ >= 900
        cudaTriggerProgrammaticLaunchCompletion();
#endif
    }
}

// Write stream, single wave (1024 blocks, all resident), streaming stores.
// blockIdx.y = expert row; in-range test = one unsigned compare per element.
// __stcs -> st.global.cs: evict-first, this data is write-once/never-reused,
// keeps the L2 drain path clean.
__global__ void __launch_bounds__(TPB, 8) masks_kernel(float4* __restrict__ out) {
#if __CUDA_ARCH__ >= 900
    cudaGridDependencySynchronize();
#endif
    const int e  = blockIdx.y;
    const int s  = g_bounds[2 * e];
    const unsigned len = (unsigned)(g_bounds[2 * e + 1] - s);

    float4* row = out + (size_t)e * ROW_V;
    const unsigned base = blockIdx.x * (TPB * ITERS) + threadIdx.x;

#pragma unroll
    for (int i = 0; i < ITERS; i++) {
        unsigned v = base + i * TPB;       // float4 index within the row
        int p = (int)(v << 2) - s;         // element offset relative to start
        float4 f;
        f.x = ((unsigned)(p    ) < len) ? 1.0f : 0.0f;
        f.y = ((unsigned)(p + 1) < len) ? 1.0f : 0.0f;
        f.z = ((unsigned)(p + 2) < len) ? 1.0f : 0.0f;
        f.w = ((unsigned)(p + 3) < len) ? 1.0f : 0.0f;
        __stcs(&row[v], f);                // st.global.cs streaming store
    }
}

extern "C" void kernel_launch(void* const* d_in, const int* in_sizes, int n_in,
                              void* d_out, int out_size) {
    const float* bound_params = (const float*)d_in[0];
    float4* out = (float4*)d_out;

    prep_kernel<<<1, 32>>>(bound_params);

    // PDL: masks pre-launches, parks at cudaGridDependencySynchronize until
    // prep's explicit trigger (bounds written + fenced).
    cudaLaunchConfig_t cfg = {};
    cfg.gridDim  = dim3(BLOCKS_X, NUM_EXPERTS);
    cfg.blockDim = dim3(TPB);
    cudaLaunchAttribute attr[1];
    attr[0].id = cudaLaunchAttributeProgrammaticStreamSerialization;
    attr[0].val.programmaticStreamSerializationAllowed = 1;
    cfg.attrs    = attr;
    cfg.numAttrs = 1;
    cudaLaunchKernelEx(&cfg, masks_kernel, out);
}